// round 1
// baseline (speedup 1.0000x reference)
#include <cuda_runtime.h>
#include <cuda_bf16.h>
#include <cstdint>

// Problem constants (fixed by setup_inputs)
#define N_ENT   100000
#define N_DRUG  2000
#define N_REL   51
#define N_EDGE  1000000
#define DIM     64
#define N_HOPS  3

// Device-global scratch (alloc-free rule)
__device__ float g_agg[N_ENT * DIM];   // segment-sum accumulator
__device__ float g_ent[N_ENT * DIM];   // current entity embedding (post-normalize)
__device__ float g_rel[N_REL * DIM];   // normalized relation embedding

// ---------------------------------------------------------------------------
// Zero the aggregation buffer (float4 stores, 1.6M threads)
// ---------------------------------------------------------------------------
__global__ void zero_agg_kernel() {
    int i = blockIdx.x * blockDim.x + threadIdx.x;
    if (i < N_ENT * DIM / 4) {
        reinterpret_cast<float4*>(g_agg)[i] = make_float4(0.f, 0.f, 0.f, 0.f);
    }
}

// ---------------------------------------------------------------------------
// Scatter: for each edge, agg[head] += ent[tail] * rel[etype]
// 16 lanes per edge, each lane handles 4 dims via float4 + red.global.add.v4
// ---------------------------------------------------------------------------
__global__ void scatter_kernel(const float* __restrict__ ent_in,
                               const float* __restrict__ rel_in,
                               const int*   __restrict__ eidx,
                               const int*   __restrict__ etype,
                               int use_global) {
    long long tid = (long long)blockIdx.x * blockDim.x + threadIdx.x;
    int e = (int)(tid >> 4);
    int q = (int)(tid & 15);
    if (e >= N_EDGE) return;

    const float* ent = use_global ? g_ent : ent_in;
    const float* rel = use_global ? g_rel : rel_in;

    int head = eidx[e];
    int tail = eidx[N_EDGE + e];
    int r    = etype[e];

    float4 a = reinterpret_cast<const float4*>(ent)[(long long)tail * 16 + q];
    float4 b = reinterpret_cast<const float4*>(rel)[r * 16 + q];

    float4 m;
    m.x = a.x * b.x;
    m.y = a.y * b.y;
    m.z = a.z * b.z;
    m.w = a.w * b.w;

    float* dst = g_agg + (long long)head * DIM + q * 4;
    asm volatile("red.global.add.v4.f32 [%0], {%1, %2, %3, %4};"
                 :: "l"(dst), "f"(m.x), "f"(m.y), "f"(m.z), "f"(m.w)
                 : "memory");
}

// ---------------------------------------------------------------------------
// Normalize each row of g_agg -> g_ent, accumulate into out_ent / out_drug.
// One warp per row, 2 floats per lane (float2), warp-shuffle reduction.
// Note: l2_normalize(segsum/denom) == l2_normalize(segsum), denom dropped.
// ---------------------------------------------------------------------------
__global__ void norm_kernel(float* __restrict__ out_ent,
                            float* __restrict__ out_drug) {
    int row  = blockIdx.x * 8 + (threadIdx.x >> 5);
    int lane = threadIdx.x & 31;
    if (row >= N_ENT) return;

    float2 v = reinterpret_cast<const float2*>(g_agg)[row * 32 + lane];
    float ss = v.x * v.x + v.y * v.y;
    #pragma unroll
    for (int o = 16; o > 0; o >>= 1)
        ss += __shfl_xor_sync(0xFFFFFFFFu, ss, o);

    float norm = sqrtf(ss);
    float inv  = 1.0f / fmaxf(norm, 1e-12f);
    float2 n;
    n.x = v.x * inv;
    n.y = v.y * inv;

    reinterpret_cast<float2*>(g_ent)[row * 32 + lane] = n;

    float2* oe = reinterpret_cast<float2*>(out_ent) + row * 32 + lane;
    float2 c = *oe;
    c.x += n.x; c.y += n.y;
    *oe = c;

    if (row < N_DRUG) {
        float2* od = reinterpret_cast<float2*>(out_drug) + row * 32 + lane;
        float2 c2 = *od;
        c2.x += n.x; c2.y += n.y;
        *od = c2;
    }
}

// ---------------------------------------------------------------------------
// Relation handling (once): g_rel = l2_normalize(rel0);
// out_rel = rel0 + 3 * g_rel   (normalization is idempotent)
// One block (32 threads) per relation row.
// ---------------------------------------------------------------------------
__global__ void rel_kernel(const float* __restrict__ rel0,
                           float* __restrict__ out_rel) {
    int row  = blockIdx.x;
    int lane = threadIdx.x;

    float2 v = reinterpret_cast<const float2*>(rel0)[row * 32 + lane];
    float ss = v.x * v.x + v.y * v.y;
    #pragma unroll
    for (int o = 16; o > 0; o >>= 1)
        ss += __shfl_xor_sync(0xFFFFFFFFu, ss, o);

    float norm = sqrtf(ss);
    float inv  = 1.0f / fmaxf(norm, 1e-12f);
    float2 n;
    n.x = v.x * inv;
    n.y = v.y * inv;

    reinterpret_cast<float2*>(g_rel)[row * 32 + lane] = n;

    float2 o2;
    o2.x = v.x + 3.0f * n.x;
    o2.y = v.y + 3.0f * n.y;
    reinterpret_cast<float2*>(out_rel)[row * 32 + lane] = o2;
}

// ---------------------------------------------------------------------------
extern "C" void kernel_launch(void* const* d_in, const int* in_sizes, int n_in,
                              void* d_out, int out_size) {
    const float* ent0  = (const float*)d_in[0];
    const float* drug0 = (const float*)d_in[1];
    const float* rel0  = (const float*)d_in[2];
    const int*   eidx  = (const int*)d_in[3];
    const int*   etype = (const int*)d_in[4];

    float* out      = (float*)d_out;
    float* out_ent  = out;
    float* out_drug = out + (size_t)N_ENT * DIM;
    float* out_rel  = out + (size_t)(N_ENT + N_DRUG) * DIM;

    // Initialize accumulators: ent_res = ent0, drug_res = drug0
    cudaMemcpyAsync(out_ent,  ent0,  (size_t)N_ENT  * DIM * sizeof(float),
                    cudaMemcpyDeviceToDevice, 0);
    cudaMemcpyAsync(out_drug, drug0, (size_t)N_DRUG * DIM * sizeof(float),
                    cudaMemcpyDeviceToDevice, 0);

    // Relations: normalize once + write final rel_res
    rel_kernel<<<N_REL, 32>>>(rel0, out_rel);

    const int zero_threads = N_ENT * DIM / 4;
    const int zero_blocks  = (zero_threads + 255) / 256;
    const long long sc_threads = (long long)N_EDGE * 16;
    const int sc_blocks = (int)((sc_threads + 255) / 256);
    const int norm_blocks = (N_ENT + 7) / 8;

    for (int hop = 0; hop < N_HOPS; hop++) {
        zero_agg_kernel<<<zero_blocks, 256>>>();
        scatter_kernel<<<sc_blocks, 256>>>(ent0, rel0, eidx, etype,
                                           hop == 0 ? 0 : 1);
        norm_kernel<<<norm_blocks, 256>>>(out_ent, out_drug);
    }
}